// round 1
// baseline (speedup 1.0000x reference)
#include <cuda_runtime.h>
#include <cuda_bf16.h>
#include <math.h>

// ---------------- problem constants ----------------
#define NNODES 40960
#define NEDGES 163840
#define NGRAPH 1024
#define F0 78
#define F1D 78
#define F2D 156
#define F3D 312

// ---------------- scratch (static device memory; no allocations) ----------
__device__ float g_B1[NNODES * F3D];        // H (aggregation output)
__device__ float g_B2[NNODES * F3D];        // h@W
__device__ float g_deg[NNODES];
__device__ float g_G[NGRAPH * F3D];         // pooled
__device__ float g_G1[NGRAPH * 1024];
__device__ float g_XC[NGRAPH * 384];        // concat buffer [g | xt1 | xt2]
__device__ float g_Y2[NGRAPH * 3872];
__device__ float g_Y1[NGRAPH * 416];
__device__ float g_F1[NGRAPH * 1024];
__device__ float g_F2[NGRAPH * 512];
__device__ float g_Wc2t[750 * 256];
__device__ float g_Wc1t[750 * 256];

// ---------------- small utility kernels ----------------
__global__ void k_deg_init(float* deg, int n) {
    int i = blockIdx.x * blockDim.x + threadIdx.x;
    if (i < n) deg[i] = 1.0f;                       // self loop
}
__global__ void k_deg_scatter(const int* __restrict__ ei, float* deg, int e) {
    int i = blockIdx.x * blockDim.x + threadIdx.x;
    if (i < e) atomicAdd(&deg[ei[e + i]], 1.0f);    // dst row
}
__global__ void k_deg_rsqrt(float* deg, int n) {
    int i = blockIdx.x * blockDim.x + threadIdx.x;
    if (i < n) deg[i] = rsqrtf(deg[i]);
}
__global__ void k_initbias(float* __restrict__ out, const float* __restrict__ b,
                           int total, int F) {
    int i = blockIdx.x * blockDim.x + threadIdx.x;
    if (i < total) out[i] = b[i % F];
}

// ---------------- edge aggregation: out[dst] += hw[src]*dinv[src]*dinv[dst] ---
__global__ void k_agg(const float* __restrict__ HW, const int* __restrict__ ei,
                      const float* __restrict__ dinv, float* __restrict__ out,
                      int F, int nE, int nN) {
    int warp = (blockIdx.x * blockDim.x + threadIdx.x) >> 5;
    int lane = threadIdx.x & 31;
    int total = nE + nN;
    if (warp >= total) return;
    int s, d;
    if (warp < nE) { s = ei[warp]; d = ei[nE + warp]; }
    else           { s = d = warp - nE; }            // self loops
    float nm = dinv[s] * dinv[d];
    const float* src = HW + (size_t)s * F;
    float*       dst = out + (size_t)d * F;
    for (int f = lane; f < F; f += 32)
        atomicAdd(&dst[f], src[f] * nm);
}

// ---------------- per-graph max pool (values relu'd, so int-bit atomicMax ok) --
__global__ void k_pool(const float* __restrict__ H, const int* __restrict__ batch,
                       float* __restrict__ g, int total, int F) {
    int i = blockIdx.x * blockDim.x + threadIdx.x;
    if (i >= total) return;
    int node = i / F, f = i - node * F;
    float v = fmaxf(H[i], 0.0f);
    atomicMax((int*)&g[(size_t)batch[node] * F + f], __float_as_int(v));
}

// ---------------- generic tiled SGEMM, fused bias/relu, C column offset -------
// C[m*ldc+coff+n] = act( (reluA? relu(A) : A) @ B + bias )
__global__ void k_sgemm(const float* __restrict__ A, const float* __restrict__ B,
                        float* __restrict__ C, int M, int N, int K,
                        const float* __restrict__ bias, int doRelu, int reluA,
                        int ldc, int coff) {
    __shared__ float As[8][64];
    __shared__ float Bs[8][64];
    int tx = threadIdx.x & 15, ty = threadIdx.x >> 4;
    int bm = blockIdx.y * 64, bn = blockIdx.x * 64;
    float acc[4][4] = {};
    for (int k0 = 0; k0 < K; k0 += 8) {
        for (int i = threadIdx.x; i < 64 * 8; i += 256) {
            int r = i >> 3, c = i & 7;
            int m = bm + r, k = k0 + c;
            float v = (m < M && k < K) ? A[(size_t)m * K + k] : 0.f;
            if (reluA) v = fmaxf(v, 0.f);
            As[c][r] = v;
        }
        for (int i = threadIdx.x; i < 8 * 64; i += 256) {
            int r = i >> 6, c = i & 63;
            int k = k0 + r, n = bn + c;
            Bs[r][c] = (k < K && n < N) ? B[(size_t)k * N + n] : 0.f;
        }
        __syncthreads();
#pragma unroll
        for (int kk = 0; kk < 8; kk++) {
            float a[4], b[4];
#pragma unroll
            for (int i = 0; i < 4; i++) a[i] = As[kk][ty * 4 + i];
#pragma unroll
            for (int j = 0; j < 4; j++) b[j] = Bs[kk][tx * 4 + j];
#pragma unroll
            for (int i = 0; i < 4; i++)
#pragma unroll
                for (int j = 0; j < 4; j++) acc[i][j] += a[i] * b[j];
        }
        __syncthreads();
    }
#pragma unroll
    for (int i = 0; i < 4; i++) {
        int m = bm + ty * 4 + i;
        if (m >= M) continue;
#pragma unroll
        for (int j = 0; j < 4; j++) {
            int n = bn + tx * 4 + j;
            if (n >= N) continue;
            float v = acc[i][j] + (bias ? bias[n] : 0.f);
            if (doRelu) v = fmaxf(v, 0.f);
            C[(size_t)m * ldc + coff + n] = v;
        }
    }
}

// ---------------- transpose Wc[32][750][8] -> Wt[750][256] -------------------
__global__ void k_transw(const float* __restrict__ W, float* __restrict__ Wt) {
    int i = blockIdx.x * blockDim.x + threadIdx.x;
    if (i >= 750 * 256) return;
    int c = i >> 8, ok = i & 255;
    int o = ok >> 3, k = ok & 7;
    Wt[i] = W[((size_t)o * 750 + c) * 8 + k];
}

// ---------------- protein branch 2: factored conv via class-histogram T ------
// T[v][o*8+k] = sum_{c: t2[b,c]==v} Wc2[o,c,k];  y2[b,o,l] = bc2[o] + sum_{v,k} T*emb[v,l+k]
__global__ void k_branch2(const int* __restrict__ t2, const float* __restrict__ Wc2t,
                          const float* __restrict__ embw, const float* __restrict__ bc2,
                          float* __restrict__ Y2) {
    __shared__ float Tl[26 * 256];
    __shared__ float embs[26 * 128];
    __shared__ int   t2s[750];
    int b = blockIdx.x, tid = threadIdx.x;
    for (int i = tid; i < 26 * 256; i += 256) Tl[i] = 0.f;
    for (int i = tid; i < 26 * 128; i += 256) embs[i] = embw[i];
    for (int i = tid; i < 750; i += 256) t2s[i] = t2[(size_t)b * 750 + i];
    __syncthreads();
    for (int c = 0; c < 750; c++)
        Tl[t2s[c] * 256 + tid] += Wc2t[(size_t)c * 256 + tid];
    __syncthreads();
    for (int idx = tid; idx < 32 * 121; idx += 256) {
        int o = idx / 121, l = idx - o * 121;
        float acc = bc2[o];
        for (int v = 0; v < 26; v++) {
#pragma unroll
            for (int k = 0; k < 8; k++)
                acc += Tl[v * 256 + o * 8 + k] * embs[v * 128 + l + k];
        }
        Y2[(size_t)b * 3872 + idx] = acc;
    }
}

// ---------------- protein branch 1: direct conv, thread=(o,k), 13 l regs -----
__global__ void k_conv1(const float* __restrict__ t1, const float* __restrict__ Wc1t,
                        const float* __restrict__ bc1, float* __restrict__ Y1) {
    __shared__ float sin_[50 * 20];
    int b = blockIdx.x, tid = threadIdx.x;
    int o = tid >> 3, k = tid & 7;
    float acc[13] = {};
    for (int c0 = 0; c0 < 750; c0 += 50) {
        for (int i = tid; i < 1000; i += 256)
            sin_[i] = t1[(size_t)b * 15000 + c0 * 20 + i];
        __syncthreads();
        for (int cc = 0; cc < 50; cc++) {
            float w = Wc1t[(size_t)(c0 + cc) * 256 + tid];
#pragma unroll
            for (int l = 0; l < 13; l++)
                acc[l] += w * sin_[cc * 20 + k + l];
        }
        __syncthreads();
    }
#pragma unroll
    for (int l = 0; l < 13; l++) {
        float v = acc[l];
        v += __shfl_down_sync(0xffffffffu, v, 4, 8);
        v += __shfl_down_sync(0xffffffffu, v, 2, 8);
        v += __shfl_down_sync(0xffffffffu, v, 1, 8);
        if (k == 0) Y1[(size_t)b * 416 + o * 13 + l] = v + bc1[o];
    }
}

// ---------------- final projection [1024,512]@[512,1] ------------------------
__global__ void k_out(const float* __restrict__ F2w, const float* __restrict__ Wo,
                      const float* __restrict__ bo, float* __restrict__ out) {
    int warp = (blockIdx.x * blockDim.x + threadIdx.x) >> 5;
    int lane = threadIdx.x & 31;
    if (warp >= NGRAPH) return;
    float s = 0.f;
    for (int i = lane; i < 512; i += 32) s += F2w[(size_t)warp * 512 + i] * Wo[i];
#pragma unroll
    for (int off = 16; off; off >>= 1) s += __shfl_down_sync(0xffffffffu, s, off);
    if (lane == 0) out[warp] = s + bo[0];
}

// ---------------- host orchestration ----------------
static inline dim3 gemm_grid(int M, int N) { return dim3((N + 63) / 64, (M + 63) / 64); }

extern "C" void kernel_launch(void* const* d_in, const int* in_sizes, int n_in,
                              void* d_out, int out_size) {
    const float* x   = (const float*)d_in[0];
    const int*   ei  = (const int*)  d_in[1];
    const int*   bat = (const int*)  d_in[2];
    const float* t1  = (const float*)d_in[3];
    const int*   t2  = (const int*)  d_in[4];
    const float *W1 = (const float*)d_in[5],  *b1 = (const float*)d_in[6];
    const float *W2 = (const float*)d_in[7],  *b2 = (const float*)d_in[8];
    const float *W3 = (const float*)d_in[9],  *b3 = (const float*)d_in[10];
    const float *Wg1= (const float*)d_in[11], *bg1= (const float*)d_in[12];
    const float *Wg2= (const float*)d_in[13], *bg2= (const float*)d_in[14];
    const float *emb= (const float*)d_in[15];
    const float *Wc2= (const float*)d_in[16], *bc2= (const float*)d_in[17];
    const float *Wxt2=(const float*)d_in[18], *bxt2=(const float*)d_in[19];
    const float *Wc1= (const float*)d_in[20], *bc1= (const float*)d_in[21];
    const float *Wxt1=(const float*)d_in[22], *bxt1=(const float*)d_in[23];
    const float *Wf1= (const float*)d_in[24], *bf1= (const float*)d_in[25];
    const float *Wf2= (const float*)d_in[26], *bf2= (const float*)d_in[27];
    const float *Wo = (const float*)d_in[28], *bo = (const float*)d_in[29];
    float* out = (float*)d_out;

    float *B1, *B2, *deg, *G, *G1, *XC, *Y2, *Y1, *Fb1, *Fb2, *Wc2t, *Wc1t;
    cudaGetSymbolAddress((void**)&B1, g_B1);
    cudaGetSymbolAddress((void**)&B2, g_B2);
    cudaGetSymbolAddress((void**)&deg, g_deg);
    cudaGetSymbolAddress((void**)&G, g_G);
    cudaGetSymbolAddress((void**)&G1, g_G1);
    cudaGetSymbolAddress((void**)&XC, g_XC);
    cudaGetSymbolAddress((void**)&Y2, g_Y2);
    cudaGetSymbolAddress((void**)&Y1, g_Y1);
    cudaGetSymbolAddress((void**)&Fb1, g_F1);
    cudaGetSymbolAddress((void**)&Fb2, g_F2);
    cudaGetSymbolAddress((void**)&Wc2t, g_Wc2t);
    cudaGetSymbolAddress((void**)&Wc1t, g_Wc1t);

    const int N = NNODES, E = NEDGES;
    const int aggBlocks = (E + N + 7) / 8;   // 8 warps / block, warp per edge

    // degree / normalization
    k_deg_init   <<<(N + 255) / 256, 256>>>(deg, N);
    k_deg_scatter<<<(E + 255) / 256, 256>>>(ei, deg, E);
    k_deg_rsqrt  <<<(N + 255) / 256, 256>>>(deg, N);

    // --- GCN layer 1: x@W1 -> agg -> (relu read downstream)
    k_sgemm<<<gemm_grid(N, F1D), 256>>>(x, W1, B2, N, F1D, F0, nullptr, 0, 0, F1D, 0);
    k_initbias<<<(N * F1D + 255) / 256, 256>>>(B1, b1, N * F1D, F1D);
    k_agg<<<aggBlocks, 256>>>(B2, ei, deg, B1, F1D, E, N);
    // --- layer 2
    k_sgemm<<<gemm_grid(N, F2D), 256>>>(B1, W2, B2, N, F2D, F1D, nullptr, 0, 1, F2D, 0);
    k_initbias<<<(N * F2D + 255) / 256, 256>>>(B1, b2, N * F2D, F2D);
    k_agg<<<aggBlocks, 256>>>(B2, ei, deg, B1, F2D, E, N);
    // --- layer 3
    k_sgemm<<<gemm_grid(N, F3D), 256>>>(B1, W3, B2, N, F3D, F2D, nullptr, 0, 1, F3D, 0);
    k_initbias<<<(N * F3D + 255) / 256, 256>>>(B1, b3, N * F3D, F3D);
    k_agg<<<aggBlocks, 256>>>(B2, ei, deg, B1, F3D, E, N);

    // --- per-graph max pool (applies relu)
    cudaMemsetAsync(G, 0, (size_t)NGRAPH * F3D * sizeof(float));
    k_pool<<<(N * F3D + 255) / 256, 256>>>(B1, bat, G, N * F3D, F3D);

    // --- graph head: g@Wg1 relu -> @Wg2 -> XC[:,0:128]
    k_sgemm<<<gemm_grid(NGRAPH, 1024), 256>>>(G, Wg1, G1, NGRAPH, 1024, F3D, bg1, 1, 0, 1024, 0);
    k_sgemm<<<gemm_grid(NGRAPH, 128), 256>>>(G1, Wg2, XC, NGRAPH, 128, 1024, bg2, 0, 0, 384, 0);

    // --- protein branch 2 (factored conv) -> XC[:,256:384]
    k_transw<<<750, 256>>>(Wc2, Wc2t);
    k_branch2<<<NGRAPH, 256>>>(t2, Wc2t, emb, bc2, Y2);
    k_sgemm<<<gemm_grid(NGRAPH, 128), 256>>>(Y2, Wxt2, XC, NGRAPH, 128, 3872, bxt2, 0, 0, 384, 256);

    // --- protein branch 1 -> XC[:,128:256]
    k_transw<<<750, 256>>>(Wc1, Wc1t);
    k_conv1<<<NGRAPH, 256>>>(t1, Wc1t, bc1, Y1);
    k_sgemm<<<gemm_grid(NGRAPH, 128), 256>>>(Y1, Wxt1, XC, NGRAPH, 128, 416, bxt1, 0, 0, 384, 128);

    // --- fusion head
    k_sgemm<<<gemm_grid(NGRAPH, 1024), 256>>>(XC, Wf1, Fb1, NGRAPH, 1024, 384, bf1, 1, 0, 1024, 0);
    k_sgemm<<<gemm_grid(NGRAPH, 512), 256>>>(Fb1, Wf2, Fb2, NGRAPH, 512, 1024, bf2, 1, 0, 512, 0);
    k_out<<<(NGRAPH * 32 + 255) / 256, 256>>>(Fb2, Wo, bo, out);
}